// round 15
// baseline (speedup 1.0000x reference)
#include <cuda_runtime.h>
#include <math.h>
#include <stdint.h>

#define Bx 4
#define Dd 64
#define Nn 4096
#define Oo 128
#define Kk 16
#define NEG 0.01f
#define NEGINF (-1.0e30f)

// ------------------------- static device scratch ---------------------------
__device__ float g_xx[Bx * Nn];
__device__ float g_ft[Bx * Nn * Dd];
__device__ float g_q[Bx * Dd * Nn];
__device__ float g_k[Bx * Dd * Nn];
__device__ float g_v[Bx * Dd * Nn];
__device__ float g_Aloc[(size_t)Bx * Nn * Oo];
__device__ float g_Bloc[(size_t)Bx * Nn * Oo];
__device__ int   g_idxb[Bx * Nn * Kk];
__device__ float g_ymax[(size_t)Bx * Nn * Oo];
__device__ float g_ymin[(size_t)Bx * Nn * Oo];
__device__ float g_z2[(size_t)Bx * Nn * Oo];
__device__ float g_z3[(size_t)Bx * Nn * Oo];
__device__ float g_fgt[Bx * Dd * Nn];
__device__ float g_p1s[512 * Oo], g_p1q[512 * Oo];
__device__ float g_p2s[256 * Oo], g_p2q[256 * Oo];
__device__ float g_p3s[1024 * Oo], g_p3q[1024 * Oo];
__device__ float g_sc1[Oo], g_sh1[Oo], g_sc2[Oo], g_sh2[Oo], g_sc3[Oo], g_sh3[Oo];

// ------------------------- helpers -----------------------------------------
__device__ __forceinline__ void tf32split_u(float x, uint32_t& hi, uint32_t& lo) {
    asm("cvt.rna.tf32.f32 %0, %1;" : "=r"(hi) : "f"(x));
    float l = x - __uint_as_float(hi);
    asm("cvt.rna.tf32.f32 %0, %1;" : "=r"(lo) : "f"(l));
}
__device__ __forceinline__ uint32_t tf32one(float x) {
    uint32_t h;
    asm("cvt.rna.tf32.f32 %0, %1;" : "=r"(h) : "f"(x));
    return h;
}
__device__ __forceinline__ void mma_m16n8k8(float* c, const uint32_t* a, const uint32_t* b) {
    asm volatile(
        "mma.sync.aligned.m16n8k8.row.col.f32.tf32.tf32.f32 "
        "{%0,%1,%2,%3}, {%4,%5,%6,%7}, {%8,%9}, {%0,%1,%2,%3};"
        : "+f"(c[0]), "+f"(c[1]), "+f"(c[2]), "+f"(c[3])
        : "r"(a[0]), "r"(a[1]), "r"(a[2]), "r"(a[3]), "r"(b[0]), "r"(b[1]));
}

// ------------------------- xx[b,n] = sum_d f^2 -----------------------------
__global__ void k_xx(const float* __restrict__ f) {
    int id = blockIdx.x * 256 + threadIdx.x;
    int b = id >> 12;
    int n = id & (Nn - 1);
    const float* fb = f + (size_t)b * Dd * Nn + n;
    float s = 0.f;
#pragma unroll
    for (int d = 0; d < Dd; d++) {
        float v = fb[(size_t)d * Nn];
        s = fmaf(v, v, s);
    }
    g_xx[id] = s;
}

// ------------------------- transpose f -> (B,N,D) --------------------------
__global__ __launch_bounds__(256) void k_tr(const float* __restrict__ f) {
    __shared__ float tile[32][33];
    int b = blockIdx.z, d0 = blockIdx.y * 32, n0 = blockIdx.x * 32;
    int tx = threadIdx.x & 31, ty = threadIdx.x >> 5;
#pragma unroll
    for (int i = 0; i < 4; i++)
        tile[ty + i * 8][tx] = f[((size_t)b * Dd + d0 + ty + i * 8) * Nn + n0 + tx];
    __syncthreads();
#pragma unroll
    for (int i = 0; i < 4; i++)
        g_ft[((size_t)b * Nn + n0 + ty + i * 8) * Dd + d0 + tx] = tile[tx][ty + i * 8];
}

// ---- fused pd (tf32 3-term) + per-row top-16, 512 threads (16 warps) ------
#define KSTA 136
#define KSTB 136
#define PDS 132
__global__ __launch_bounds__(512) void k_pdtk(const float* __restrict__ f) {
    extern __shared__ uint32_t dsm[];
    uint32_t* sAh = dsm;                                // 64*136
    uint32_t* sAl = dsm + 64 * KSTA;                    // 64*136
    uint32_t* sBh = dsm + 2 * 64 * KSTA;                // 32*136
    uint32_t* sBl = dsm + 2 * 64 * KSTA + 32 * KSTB;    // 32*136
    float* sPD = (float*)(dsm + 2 * 64 * KSTA + 2 * 32 * KSTB);  // 128*132
    float* sMv = (float*)sBh;   // merge reuse: 512*16 = 8192 <= 8704 words
    int*   sMi = (int*)sPD;     // merge reuse: 8192 <= 16896 words
    __shared__ float sXM[128], sXN[128];
    int t = threadIdx.x, lane = t & 31, wid = t >> 5;
    int wm = wid & 3, wn = wid >> 2;          // wn 0..3
    int gid = lane >> 2, ctg = lane & 3;
    int b = blockIdx.y, m0 = blockIdx.x * 128;
    const float* Ap = f + (size_t)b * Dd * Nn;
    if (t < 128) sXM[t] = g_xx[b * Nn + m0 + t];
    // hoisted A fill: full K=64, 3-term split
#pragma unroll
    for (int i = 0; i < 16; i++) {
        int e = t + i * 512;
        int d = e >> 7, m = e & 127;
        float a = Ap[(size_t)d * Nn + m0 + m];
        uint32_t hi, lo;
        tf32split_u(a, hi, lo);
        sAh[d * KSTA + m] = hi;
        sAl[d * KSTA + m] = lo;
    }
    // per-thread top-16 (unsorted set + threshold)
    float tv[16];
    int ti[16];
#pragma unroll
    for (int j = 0; j < 16; j++) { tv[j] = NEGINF; ti[j] = (1 << 30) + j; }
    float minv = NEGINF;
    int row = t >> 2, q = t & 3;

    for (int nt = 0; nt < 32; nt++) {
        int n0 = nt * 128;
        float acc[2][4][4] = {};
        __syncthreads();
        if (t < 128) sXN[t] = g_xx[b * Nn + n0 + t];
#pragma unroll
        for (int kc = 0; kc < 2; kc++) {
            int kc0 = kc * 32;
            if (kc) __syncthreads();
#pragma unroll
            for (int i = 0; i < 8; i++) {
                int e = t + i * 512;
                int d = e >> 7, m = e & 127;
                float bb = Ap[(size_t)(kc0 + d) * Nn + n0 + m];
                uint32_t hi, lo;
                tf32split_u(bb, hi, lo);
                sBh[d * KSTB + m] = hi;
                sBl[d * KSTB + m] = lo;
            }
            __syncthreads();
#pragma unroll
            for (int ks = 0; ks < 4; ks++) {
                int kb = ks * 8 + ctg;
                uint32_t ah[2][4], al[2][4];
#pragma unroll
                for (int mi = 0; mi < 2; mi++) {
                    int mb = wm * 32 + mi * 16 + gid;
                    ah[mi][0] = sAh[(kc0 + kb) * KSTA + mb];
                    ah[mi][1] = sAh[(kc0 + kb) * KSTA + mb + 8];
                    ah[mi][2] = sAh[(kc0 + kb + 4) * KSTA + mb];
                    ah[mi][3] = sAh[(kc0 + kb + 4) * KSTA + mb + 8];
                    al[mi][0] = sAl[(kc0 + kb) * KSTA + mb];
                    al[mi][1] = sAl[(kc0 + kb) * KSTA + mb + 8];
                    al[mi][2] = sAl[(kc0 + kb + 4) * KSTA + mb];
                    al[mi][3] = sAl[(kc0 + kb + 4) * KSTA + mb + 8];
                }
#pragma unroll
                for (int nf = 0; nf < 4; nf++) {
                    int nb = wn * 32 + nf * 8 + gid;
                    uint32_t bh[2], bl[2];
                    bh[0] = sBh[kb * KSTB + nb];
                    bh[1] = sBh[(kb + 4) * KSTB + nb];
                    bl[0] = sBl[kb * KSTB + nb];
                    bl[1] = sBl[(kb + 4) * KSTB + nb];
#pragma unroll
                    for (int mi = 0; mi < 2; mi++) {
                        mma_m16n8k8(acc[mi][nf], ah[mi], bh);
                        mma_m16n8k8(acc[mi][nf], ah[mi], bl);
                        mma_m16n8k8(acc[mi][nf], al[mi], bh);
                    }
                }
            }
        }
        // pd tile -> smem (same transform/order as validated k_mm)
#pragma unroll
        for (int mi = 0; mi < 2; mi++) {
#pragma unroll
            for (int nf = 0; nf < 4; nf++) {
                float* c = acc[mi][nf];
                int ml = wm * 32 + mi * 16 + gid;
                int nl = wn * 32 + nf * 8 + 2 * ctg;
                sPD[ml * PDS + nl]           = 2.f * c[0] - sXM[ml] - sXN[nl];
                sPD[ml * PDS + nl + 1]       = 2.f * c[1] - sXM[ml] - sXN[nl + 1];
                sPD[(ml + 8) * PDS + nl]     = 2.f * c[2] - sXM[ml + 8] - sXN[nl];
                sPD[(ml + 8) * PDS + nl + 1] = 2.f * c[3] - sXM[ml + 8] - sXN[nl + 1];
            }
        }
        __syncthreads();
        // selection scan: 4 threads/row, interleaved cols q + 4*c2
        const float* prow = sPD + row * PDS;
#pragma unroll 4
        for (int c2 = 0; c2 < 32; c2++) {
            int col = q + 4 * c2;
            float v = prow[col];
            if (v > minv) {
                int idx = n0 + col;
                int evi = -1;
#pragma unroll
                for (int j = 0; j < 16; j++)
                    if (tv[j] == minv && ti[j] > evi) evi = ti[j];
#pragma unroll
                for (int j = 0; j < 16; j++)
                    if (tv[j] == minv && ti[j] == evi) { tv[j] = v; ti[j] = idx; }
                float nm = tv[0];
#pragma unroll
                for (int j = 1; j < 16; j++) nm = fminf(nm, tv[j]);
                minv = nm;
            }
        }
    }
    // merge 4 sets of 16 per row with jax tie-break (val desc, idx asc)
    __syncthreads();
#pragma unroll
    for (int j = 0; j < 16; j++) { sMv[t * 16 + j] = tv[j]; sMi[t * 16 + j] = ti[j]; }
    __syncthreads();
    if (t < 128) {
        int base = t * 64;   // 64 contiguous entries: 4 sets of this row
        uint64_t taken = 0;
        int* outp = g_idxb + ((size_t)(b * Nn + m0 + t)) * Kk;
        for (int r = 0; r < Kk; r++) {
            float bv = NEGINF;
            int bi = 1 << 30, bp = 0;
            for (int e2 = 0; e2 < 64; e2++) {
                if ((taken >> e2) & 1ull) continue;
                float v = sMv[base + e2];
                int id = sMi[base + e2];
                if (v > bv || (v == bv && id < bi)) { bv = v; bi = id; bp = e2; }
            }
            taken |= 1ull << bp;
            outp[r] = bi;
        }
    }
}

// -------- A = W[:, :64] . x, Bv = W[:, 64:128] . x  ------------------------
__global__ __launch_bounds__(256) void k_projAB(const float* __restrict__ wl) {
    __shared__ float sF[64][64];
    int bn0 = blockIdx.x * 64;
    int t = threadIdx.x;
    for (int e = t; e < 4096; e += 256) {
        int n = e >> 6, d = e & 63;
        sF[n][d] = g_ft[(size_t)(bn0 + n) * Dd + d];
    }
    __syncthreads();
    int half = t >> 7, o = t & 127;
    float wr[64];
#pragma unroll
    for (int d = 0; d < 64; d++) wr[d] = wl[o * 129 + half * 64 + d];
    float* dst = half ? g_Bloc : g_Aloc;
    for (int nn = 0; nn < 64; nn++) {
        float acc = 0.f;
#pragma unroll
        for (int d = 0; d < 64; d++) acc = fmaf(wr[d], sF[nn][d], acc);
        dst[(size_t)(bn0 + nn) * Oo + o] = acc;
    }
}

// --- gather neighbors, dist, y = A + Bv[j] + w_last*dist; max/min + stats --
__global__ __launch_bounds__(128) void k_intra(const float* __restrict__ wl) {
    __shared__ float sCen[64];
    __shared__ float sPart[16][8];
    __shared__ float sDist[16];
    __shared__ int sJ[16];
    int t = threadIdx.x;
    float wlast = wl[t * 129 + 128];
    float accS = 0.f, accQ = 0.f;
    for (int g = 0; g < 32; g++) {
        int bn = blockIdx.x * 32 + g;
        int b = bn >> 12;
        if (t < 64) sCen[t] = g_ft[(size_t)bn * Dd + t];
        __syncthreads();
        {
            int k = t >> 3, dg = t & 7;
            int j = g_idxb[(size_t)bn * Kk + k];
            const float* nr = g_ft + ((size_t)b * Nn + j) * Dd + dg * 8;
            float p = 0.f;
#pragma unroll
            for (int d = 0; d < 8; d++) {
                float df = nr[d] - sCen[dg * 8 + d];
                p = fmaf(df, df, p);
            }
            sPart[k][dg] = p;
            if (dg == 0) sJ[k] = j;
        }
        __syncthreads();
        if (t < 16) {
            float s = 0.f;
#pragma unroll
            for (int d = 0; d < 8; d++) s += sPart[t][d];
            sDist[t] = sqrtf(s);
        }
        __syncthreads();
        float a = g_Aloc[(size_t)bn * Oo + t];
        float mx = NEGINF, mn = -NEGINF;
#pragma unroll
        for (int kk = 0; kk < Kk; kk++) {
            int jj = sJ[kk];
            float y = a + g_Bloc[((size_t)b * Nn + jj) * Oo + t] + wlast * sDist[kk];
            mx = fmaxf(mx, y);
            mn = fminf(mn, y);
            accS += y;
            accQ = fmaf(y, y, accQ);
        }
        g_ymax[(size_t)bn * Oo + t] = mx;
        g_ymin[(size_t)bn * Oo + t] = mn;
        __syncthreads();
    }
    g_p1s[(size_t)blockIdx.x * Oo + t] = accS;
    g_p1q[(size_t)blockIdx.x * Oo + t] = accQ;
}

// ---------------- q,k,v projections (coalesced writes) ---------------------
__global__ __launch_bounds__(256) void k_qkv(const float* __restrict__ f,
    const float* __restrict__ wq, const float* __restrict__ bq,
    const float* __restrict__ wk, const float* __restrict__ bk,
    const float* __restrict__ wv, const float* __restrict__ bv) {
    extern __shared__ float qsm[];
    float* sF = qsm;                 // [64][65]
    float* sW = qsm + 64 * 65;       // [192][64]
    float* sBias = sW + 192 * 64;    // [192]
    int t = threadIdx.x, lane = t & 31, wid = t >> 5;
    int b = blockIdx.y, n0 = blockIdx.x * 64;
    const float* fb = f + (size_t)b * Dd * Nn;
    for (int e = t; e < 64 * 64; e += 256) {
        int d = e >> 6, nn = e & 63;
        sF[d * 65 + nn] = fb[(size_t)d * Nn + n0 + nn];
    }
    for (int e = t; e < 192 * 64; e += 256) {
        int r = e >> 6, d = e & 63;
        const float* W = r < 64 ? wq : (r < 128 ? wk : wv);
        sW[e] = W[(r & 63) * 64 + d];
    }
    if (t < 192) sBias[t] = t < 64 ? bq[t] : (t < 128 ? bk[t - 64] : bv[t - 128]);
    __syncthreads();
#pragma unroll 4
    for (int j = 0; j < 24; j++) {
        int r = wid + 8 * j;
        const float* wr = sW + r * 64;
        float a0 = sBias[r], a1 = a0;
#pragma unroll 16
        for (int d = 0; d < 64; d++) {
            float w = wr[d];
            a0 = fmaf(w, sF[d * 65 + lane], a0);
            a1 = fmaf(w, sF[d * 65 + lane + 32], a1);
        }
        int mat = r >> 6, o = r & 63;
        float* outp = (mat == 0 ? g_q : (mat == 1 ? g_k : g_v)) + ((size_t)b * Dd + o) * Nn + n0;
        outp[lane] = a0;
        outp[lane + 32] = a1;
    }
}

// ----- flash attention: fgt = softmax(qk/8) @ v, no S materialization ------
__global__ __launch_bounds__(256) void k_flash() {
    extern __shared__ uint32_t fsm[];
    uint32_t* sK = fsm;                    // 64*72
    uint32_t* sP = fsm + 64 * 72;          // 128*72
    uint32_t* sV = fsm + 64 * 72 + 128 * 72;
    float* sQ = (float*)fsm;               // prologue only: [64][136]
    float* sO = (float*)fsm;               // epilogue only: [64][129]
    int t = threadIdx.x, lane = t & 31, wid = t >> 5;
    int gid = lane >> 2, ctg = lane & 3;
    int b = blockIdx.y, m0 = blockIdx.x * 128;
    int mwb = wid * 16;
    const float* qb = g_q + (size_t)b * Dd * Nn;
    const float* kb_ = g_k + (size_t)b * Dd * Nn;
    const float* vb = g_v + (size_t)b * Dd * Nn;

#pragma unroll
    for (int i = 0; i < 32; i++) {
        int e = t + i * 256;
        int d = e >> 7, m = e & 127;
        sQ[d * 136 + m] = qb[(size_t)d * Nn + m0 + m] * 0.125f;
    }
    __syncthreads();
    uint32_t qf[8][4];
#pragma unroll
    for (int ks = 0; ks < 8; ks++) {
        int kb = ks * 8 + ctg;
        int mb = mwb + gid;
        qf[ks][0] = tf32one(sQ[kb * 136 + mb]);
        qf[ks][1] = tf32one(sQ[kb * 136 + mb + 8]);
        qf[ks][2] = tf32one(sQ[(kb + 4) * 136 + mb]);
        qf[ks][3] = tf32one(sQ[(kb + 4) * 136 + mb + 8]);
    }

    float mo0 = NEGINF, mo1 = NEGINF, l0 = 0.f, l1 = 0.f;
    float oacc[8][4] = {};
    for (int nc = 0; nc < 64; nc++) {
        int n0 = nc * 64;
        __syncthreads();
#pragma unroll
        for (int i = 0; i < 16; i++) {
            int e = t + i * 256;
            int d = e >> 6, nn = e & 63;
            sK[d * 72 + nn] = tf32one(kb_[(size_t)d * Nn + n0 + nn]);
            sV[d * 72 + nn] = tf32one(vb[(size_t)d * Nn + n0 + nn]);
        }
        __syncthreads();
        float c[8][4] = {};
#pragma unroll
        for (int ks = 0; ks < 8; ks++) {
            int kb = ks * 8 + ctg;
#pragma unroll
            for (int nf = 0; nf < 8; nf++) {
                int nb = nf * 8 + gid;
                uint32_t bb[2];
                bb[0] = sK[kb * 72 + nb];
                bb[1] = sK[(kb + 4) * 72 + nb];
                mma_m16n8k8(c[nf], qf[ks], bb);
            }
        }
        float tm0 = NEGINF, tm1 = NEGINF;
#pragma unroll
        for (int nf = 0; nf < 8; nf++) {
            tm0 = fmaxf(tm0, fmaxf(c[nf][0], c[nf][1]));
            tm1 = fmaxf(tm1, fmaxf(c[nf][2], c[nf][3]));
        }
#pragma unroll
        for (int off = 1; off <= 2; off <<= 1) {
            tm0 = fmaxf(tm0, __shfl_xor_sync(0xffffffffu, tm0, off));
            tm1 = fmaxf(tm1, __shfl_xor_sync(0xffffffffu, tm1, off));
        }
        float mn0 = fmaxf(mo0, tm0), mn1 = fmaxf(mo1, tm1);
        float s0 = __expf(mo0 - mn0), s1 = __expf(mo1 - mn1);
        float sum0 = 0.f, sum1 = 0.f;
#pragma unroll
        for (int nf = 0; nf < 8; nf++) {
            float p00 = __expf(c[nf][0] - mn0);
            float p01 = __expf(c[nf][1] - mn0);
            float p10 = __expf(c[nf][2] - mn1);
            float p11 = __expf(c[nf][3] - mn1);
            sum0 += p00 + p01;
            sum1 += p10 + p11;
            int nl = nf * 8 + 2 * ctg;
            sP[(mwb + gid) * 72 + nl]     = tf32one(p00);
            sP[(mwb + gid) * 72 + nl + 1] = tf32one(p01);
            sP[(mwb + gid + 8) * 72 + nl]     = tf32one(p10);
            sP[(mwb + gid + 8) * 72 + nl + 1] = tf32one(p11);
        }
#pragma unroll
        for (int off = 1; off <= 2; off <<= 1) {
            sum0 += __shfl_xor_sync(0xffffffffu, sum0, off);
            sum1 += __shfl_xor_sync(0xffffffffu, sum1, off);
        }
        l0 = l0 * s0 + sum0;
        l1 = l1 * s1 + sum1;
#pragma unroll
        for (int nf = 0; nf < 8; nf++) {
            oacc[nf][0] *= s0; oacc[nf][1] *= s0;
            oacc[nf][2] *= s1; oacc[nf][3] *= s1;
        }
        __syncwarp();
#pragma unroll
        for (int ks = 0; ks < 8; ks++) {
            int kb = ks * 8 + ctg;
            uint32_t a[4];
            a[0] = sP[(mwb + gid) * 72 + kb];
            a[1] = sP[(mwb + gid + 8) * 72 + kb];
            a[2] = sP[(mwb + gid) * 72 + kb + 4];
            a[3] = sP[(mwb + gid + 8) * 72 + kb + 4];
#pragma unroll
            for (int nf = 0; nf < 8; nf++) {
                int nb = nf * 8 + gid;
                uint32_t bb[2];
                bb[0] = sV[nb * 72 + kb];
                bb[1] = sV[nb * 72 + kb + 4];
                mma_m16n8k8(oacc[nf], a, bb);
            }
        }
        mo0 = mn0; mo1 = mn1;
    }
    float is0 = 1.0f / l0, is1 = 1.0f / l1;
    __syncthreads();
#pragma unroll
    for (int nf = 0; nf < 8; nf++) {
        int d0 = nf * 8 + 2 * ctg;
        int ml = mwb + gid;
        sO[d0 * 129 + ml]           = oacc[nf][0] * is0;
        sO[(d0 + 1) * 129 + ml]     = oacc[nf][1] * is0;
        sO[d0 * 129 + ml + 8]       = oacc[nf][2] * is1;
        sO[(d0 + 1) * 129 + ml + 8] = oacc[nf][3] * is1;
    }
    __syncthreads();
#pragma unroll
    for (int i = 0; i < 32; i++) {
        int e = t + i * 256;
        int d = e >> 7, m = e & 127;
        g_fgt[((size_t)b * Dd + d) * Nn + m0 + m] = sO[d * 129 + m];
    }
}

// ------------------- inter pre-bn: z2 = w_sem . fgt ------------------------
__global__ __launch_bounds__(128) void k_inter(const float* __restrict__ wsem) {
    __shared__ float sF[64][64];
    int b = blockIdx.y, n0 = blockIdx.x * 64, t = threadIdx.x;
    const float* fb = g_fgt + (size_t)b * Dd * Nn;
    for (int e = t; e < 4096; e += 128) {
        int d = e >> 6, nn = e & 63;
        sF[d][nn] = fb[(size_t)d * Nn + n0 + nn];
    }
    __syncthreads();
    float wr[64];
#pragma unroll
    for (int d = 0; d < 64; d++) wr[d] = wsem[t * 64 + d];
    float aS = 0.f, aQ = 0.f;
    for (int nn = 0; nn < 64; nn++) {
        float acc = 0.f;
#pragma unroll
        for (int d = 0; d < 64; d++) acc = fmaf(wr[d], sF[d][nn], acc);
        g_z2[((size_t)b * Nn + n0 + nn) * Oo + t] = acc;
        aS += acc;
        aQ = fmaf(acc, acc, aQ);
    }
    int blk = blockIdx.y * gridDim.x + blockIdx.x;
    g_p2s[(size_t)blk * Oo + t] = aS;
    g_p2q[(size_t)blk * Oo + t] = aQ;
}

// --------- bn stat finalize ------------------------------------------------
__global__ void k_bnstats(int which, int nblk, float invcnt,
                          const float* __restrict__ gamma, const float* __restrict__ beta) {
    int o = threadIdx.x;
    const float *ps, *pq;
    float *sc, *sh;
    if (which == 1) { ps = g_p1s; pq = g_p1q; sc = g_sc1; sh = g_sh1; }
    else if (which == 2) { ps = g_p2s; pq = g_p2q; sc = g_sc2; sh = g_sh2; }
    else { ps = g_p3s; pq = g_p3q; sc = g_sc3; sh = g_sh3; }
    float s = 0.f, q = 0.f;
    for (int i = 0; i < nblk; i++) {
        s += ps[(size_t)i * Oo + o];
        q += pq[(size_t)i * Oo + o];
    }
    float mean = s * invcnt;
    float var = q * invcnt - mean * mean;
    float scl = gamma[o] / sqrtf(var + 1e-5f);
    sc[o] = scl;
    sh[o] = beta[o] - mean * scl;
}

// --------- z3 = w_full . [lrelu(bn1(intra)); lrelu(bn2(inter))] ------------
__global__ __launch_bounds__(128) void k_z3(const float* __restrict__ wfull) {
    __shared__ float sC[16][256];
    __shared__ float sW[32][129];
    int bn0 = blockIdx.x * 16, t = threadIdx.x;
    for (int e = t; e < 16 * 256; e += 128) {
        int n = e >> 8, c = e & 255;
        int bn = bn0 + n;
        float pre;
        if (c < 128) {
            float s1 = g_sc1[c];
            float ym = (s1 >= 0.f) ? g_ymax[(size_t)bn * Oo + c] : g_ymin[(size_t)bn * Oo + c];
            pre = fmaf(s1, ym, g_sh1[c]);
        } else {
            int o = c - 128;
            pre = fmaf(g_sc2[o], g_z2[(size_t)bn * Oo + o], g_sh2[o]);
        }
        sC[n][c] = pre >= 0.f ? pre : NEG * pre;
    }
    float acc[16] = {};
    for (int ch = 0; ch < 8; ch++) {
        __syncthreads();
        for (int e = t; e < 32 * 128; e += 128) {
            int o = e >> 5, c = e & 31;
            sW[c][o] = wfull[(size_t)o * 256 + ch * 32 + c];
        }
        __syncthreads();
#pragma unroll 4
        for (int c = 0; c < 32; c++) {
            float w = sW[c][t];
            int cg = ch * 32 + c;
#pragma unroll
            for (int n = 0; n < 16; n++) acc[n] = fmaf(w, sC[n][cg], acc[n]);
        }
    }
    float aS = 0.f, aQ = 0.f;
#pragma unroll
    for (int n = 0; n < 16; n++) {
        float z = acc[n];
        g_z3[(size_t)(bn0 + n) * Oo + t] = z;
        aS += z;
        aQ = fmaf(z, z, aQ);
    }
    g_p3s[(size_t)blockIdx.x * Oo + t] = aS;
    g_p3q[(size_t)blockIdx.x * Oo + t] = aQ;
}

// --------- out[b,o,n] = lrelu(bn3(z3)) with transpose ----------------------
__global__ __launch_bounds__(256) void k_out(float* __restrict__ out) {
    __shared__ float tile[32][33];
    int b = blockIdx.z, o0 = blockIdx.y * 32, n0 = blockIdx.x * 32;
    int tx = threadIdx.x & 31, ty = threadIdx.x >> 5;
    float scl = g_sc3[o0 + tx], sh = g_sh3[o0 + tx];
#pragma unroll
    for (int i = 0; i < 4; i++) {
        int n = n0 + ty + i * 8;
        float v = fmaf(scl, g_z3[((size_t)b * Nn + n) * Oo + o0 + tx], sh);
        tile[ty + i * 8][tx] = v >= 0.f ? v : NEG * v;
    }
    __syncthreads();
#pragma unroll
    for (int i = 0; i < 4; i++) {
        int o = o0 + ty + i * 8;
        out[((size_t)b * Oo + o) * Nn + n0 + tx] = tile[tx][ty + i * 8];
    }
}

// ---------------------------------------------------------------------------
extern "C" void kernel_launch(void* const* d_in, const int* in_sizes, int n_in,
                              void* d_out, int out_size) {
    const float* f       = (const float*)d_in[0];
    const float* w_local = (const float*)d_in[1];
    const float* g_local = (const float*)d_in[2];
    const float* b_local = (const float*)d_in[3];
    const float* w_sem   = (const float*)d_in[4];
    const float* g_sem   = (const float*)d_in[5];
    const float* b_sem   = (const float*)d_in[6];
    const float* w_full  = (const float*)d_in[7];
    const float* g_full  = (const float*)d_in[8];
    const float* b_full  = (const float*)d_in[9];
    const float* wq = (const float*)d_in[10];
    const float* bq = (const float*)d_in[11];
    const float* wk = (const float*)d_in[12];
    const float* bk = (const float*)d_in[13];
    const float* wv = (const float*)d_in[14];
    const float* bv = (const float*)d_in[15];
    float* out = (float*)d_out;

    const int PD_SMEM = (2 * 64 * KSTA + 2 * 32 * KSTB + 128 * PDS) * 4;  // 172032 B
    const int FL_SMEM = (64 + 128 + 64) * 72 * 4;                         // 73728 B
    const int QK_SMEM = (64 * 65 + 192 * 64 + 192) * 4;                   // 66560 B
    cudaFuncSetAttribute(k_pdtk, cudaFuncAttributeMaxDynamicSharedMemorySize, PD_SMEM);
    cudaFuncSetAttribute(k_flash, cudaFuncAttributeMaxDynamicSharedMemorySize, FL_SMEM);
    cudaFuncSetAttribute(k_qkv, cudaFuncAttributeMaxDynamicSharedMemorySize, QK_SMEM);

    k_xx<<<64, 256>>>(f);
    k_tr<<<dim3(Nn / 32, Dd / 32, Bx), 256>>>(f);
    k_pdtk<<<dim3(32, Bx), 512, PD_SMEM>>>(f);
    k_projAB<<<Bx * Nn / 64, 256>>>(w_local);
    k_intra<<<Bx * Nn / 32, 128>>>(w_local);
    k_bnstats<<<1, 128>>>(1, 512, 1.0f / (Bx * Nn * Kk), g_local, b_local);
    k_qkv<<<dim3(64, Bx), 256, QK_SMEM>>>(f, wq, bq, wk, bk, wv, bv);
    k_flash<<<dim3(32, Bx), 256, FL_SMEM>>>();
    k_inter<<<dim3(64, Bx), 128>>>(w_sem);
    k_bnstats<<<1, 128>>>(2, 256, 1.0f / (Bx * Nn), g_sem, b_sem);
    k_z3<<<Bx * Nn / 16, 128>>>(w_full);
    k_bnstats<<<1, 128>>>(3, 1024, 1.0f / (Bx * Nn), g_full, b_full);
    k_out<<<dim3(Nn / 32, Oo / 32, Bx), 256>>>(out);
}

// round 16
// speedup vs baseline: 1.2412x; 1.2412x over previous
#include <cuda_runtime.h>
#include <math.h>
#include <stdint.h>

#define Bx 4
#define Dd 64
#define Nn 4096
#define Oo 128
#define Kk 16
#define NEG 0.01f
#define NEGINF (-1.0e30f)

// ------------------------- static device scratch ---------------------------
__device__ float g_S[(size_t)Bx * Nn * Nn];
__device__ float g_xx[Bx * Nn];
__device__ float g_ft[Bx * Nn * Dd];
__device__ float g_q[Bx * Dd * Nn];
__device__ float g_k[Bx * Dd * Nn];
__device__ float g_v[Bx * Dd * Nn];
__device__ float g_Aloc[(size_t)Bx * Nn * Oo];
__device__ float g_Bloc[(size_t)Bx * Nn * Oo];
__device__ int   g_idxb[Bx * Nn * Kk];
__device__ float g_ymax[(size_t)Bx * Nn * Oo];
__device__ float g_ymin[(size_t)Bx * Nn * Oo];
__device__ float g_z2[(size_t)Bx * Nn * Oo];
__device__ float g_z3[(size_t)Bx * Nn * Oo];
__device__ float g_fgt[Bx * Dd * Nn];
__device__ float g_p1s[512 * Oo], g_p1q[512 * Oo];
__device__ float g_p2s[256 * Oo], g_p2q[256 * Oo];
__device__ float g_p3s[1024 * Oo], g_p3q[1024 * Oo];
__device__ float g_sc1[Oo], g_sh1[Oo], g_sc2[Oo], g_sh2[Oo], g_sc3[Oo], g_sh3[Oo];

// ------------------------- helpers -----------------------------------------
__device__ __forceinline__ void tf32split_u(float x, uint32_t& hi, uint32_t& lo) {
    asm("cvt.rna.tf32.f32 %0, %1;" : "=r"(hi) : "f"(x));
    float l = x - __uint_as_float(hi);
    asm("cvt.rna.tf32.f32 %0, %1;" : "=r"(lo) : "f"(l));
}
__device__ __forceinline__ uint32_t tf32one(float x) {
    uint32_t h;
    asm("cvt.rna.tf32.f32 %0, %1;" : "=r"(h) : "f"(x));
    return h;
}
__device__ __forceinline__ void mma_m16n8k8(float* c, const uint32_t* a, const uint32_t* b) {
    asm volatile(
        "mma.sync.aligned.m16n8k8.row.col.f32.tf32.tf32.f32 "
        "{%0,%1,%2,%3}, {%4,%5,%6,%7}, {%8,%9}, {%0,%1,%2,%3};"
        : "+f"(c[0]), "+f"(c[1]), "+f"(c[2]), "+f"(c[3])
        : "r"(a[0]), "r"(a[1]), "r"(a[2]), "r"(a[3]), "r"(b[0]), "r"(b[1]));
}

// ------------------------- xx[b,n] = sum_d f^2 -----------------------------
__global__ void k_xx(const float* __restrict__ f) {
    int id = blockIdx.x * 256 + threadIdx.x;
    int b = id >> 12;
    int n = id & (Nn - 1);
    const float* fb = f + (size_t)b * Dd * Nn + n;
    float s = 0.f;
#pragma unroll
    for (int d = 0; d < Dd; d++) {
        float v = fb[(size_t)d * Nn];
        s = fmaf(v, v, s);
    }
    g_xx[id] = s;
}

// ------------------------- transpose f -> (B,N,D) --------------------------
__global__ __launch_bounds__(256) void k_tr(const float* __restrict__ f) {
    __shared__ float tile[32][33];
    int b = blockIdx.z, d0 = blockIdx.y * 32, n0 = blockIdx.x * 32;
    int tx = threadIdx.x & 31, ty = threadIdx.x >> 5;
#pragma unroll
    for (int i = 0; i < 4; i++)
        tile[ty + i * 8][tx] = f[((size_t)b * Dd + d0 + ty + i * 8) * Nn + n0 + tx];
    __syncthreads();
#pragma unroll
    for (int i = 0; i < 4; i++)
        g_ft[((size_t)b * Nn + n0 + ty + i * 8) * Dd + d0 + tx] = tile[tx][ty + i * 8];
}

// -------- warp-MMA tf32 GEMM: pd (3-term split) -> g_S ---------------------
#define KST 136
__global__ __launch_bounds__(256, 2) void k_mm(const float* __restrict__ f) {
    extern __shared__ uint32_t dsm[];
    __shared__ float sXM[128], sXN[128];
    uint32_t* sAh = dsm;
    uint32_t* sAl = dsm + 32 * KST;
    uint32_t* sBh = dsm + 64 * KST;
    uint32_t* sBl = dsm + 96 * KST;
    int t = threadIdx.x, lane = t & 31, wid = t >> 5;
    int wm = wid & 3, wn = wid >> 2;
    int gid = lane >> 2, ctg = lane & 3;
    int b = blockIdx.z, m0 = blockIdx.y * 128, n0 = blockIdx.x * 128;
    const float* Ap = f + (size_t)b * Dd * Nn;
    if (t < 128) sXM[t] = g_xx[b * Nn + m0 + t];
    else sXN[t - 128] = g_xx[b * Nn + n0 + t - 128];
    float acc[2][8][4] = {};
#pragma unroll
    for (int kc = 0; kc < 2; kc++) {
        int kc0 = kc * 32;
        __syncthreads();
#pragma unroll
        for (int i = 0; i < 16; i++) {
            int e = t + i * 256;
            int d = e >> 7, m = e & 127;
            float a  = Ap[(size_t)(kc0 + d) * Nn + m0 + m];
            float bb = Ap[(size_t)(kc0 + d) * Nn + n0 + m];
            uint32_t hi, lo;
            tf32split_u(a, hi, lo);  sAh[d * KST + m] = hi; sAl[d * KST + m] = lo;
            tf32split_u(bb, hi, lo); sBh[d * KST + m] = hi; sBl[d * KST + m] = lo;
        }
        __syncthreads();
#pragma unroll
        for (int ks = 0; ks < 4; ks++) {
            int kb = ks * 8 + ctg;
            uint32_t ah[2][4], al[2][4];
#pragma unroll
            for (int mi = 0; mi < 2; mi++) {
                int mb = wm * 32 + mi * 16 + gid;
                ah[mi][0] = sAh[kb * KST + mb];
                ah[mi][1] = sAh[kb * KST + mb + 8];
                ah[mi][2] = sAh[(kb + 4) * KST + mb];
                ah[mi][3] = sAh[(kb + 4) * KST + mb + 8];
                al[mi][0] = sAl[kb * KST + mb];
                al[mi][1] = sAl[kb * KST + mb + 8];
                al[mi][2] = sAl[(kb + 4) * KST + mb];
                al[mi][3] = sAl[(kb + 4) * KST + mb + 8];
            }
#pragma unroll
            for (int nf = 0; nf < 8; nf++) {
                int nb = wn * 64 + nf * 8 + gid;
                uint32_t bh[2], bl[2];
                bh[0] = sBh[kb * KST + nb];
                bh[1] = sBh[(kb + 4) * KST + nb];
                bl[0] = sBl[kb * KST + nb];
                bl[1] = sBl[(kb + 4) * KST + nb];
#pragma unroll
                for (int mi = 0; mi < 2; mi++) {
                    mma_m16n8k8(acc[mi][nf], ah[mi], bh);
                    mma_m16n8k8(acc[mi][nf], ah[mi], bl);
                    mma_m16n8k8(acc[mi][nf], al[mi], bh);
                }
            }
        }
    }
    float* outp = g_S + (size_t)b * Nn * Nn;
#pragma unroll
    for (int mi = 0; mi < 2; mi++) {
#pragma unroll
        for (int nf = 0; nf < 8; nf++) {
            float* c = acc[mi][nf];
            int ml = wm * 32 + mi * 16 + gid;
            int nl = wn * 64 + nf * 8 + 2 * ctg;
            float2 v0 = { 2.f * c[0] - sXM[ml] - sXN[nl],
                          2.f * c[1] - sXM[ml] - sXN[nl + 1] };
            float2 v1 = { 2.f * c[2] - sXM[ml + 8] - sXN[nl],
                          2.f * c[3] - sXM[ml + 8] - sXN[nl + 1] };
            *(float2*)&outp[(size_t)(m0 + ml) * Nn + n0 + nl] = v0;
            *(float2*)&outp[(size_t)(m0 + ml + 8) * Nn + n0 + nl] = v1;
        }
    }
}

// -------------- top-16 per row via 4-pass radix select ---------------------
__global__ __launch_bounds__(256) void k_topk() {
    int row = blockIdx.x;
    int t = threadIdx.x, lane = t & 31, wid = t >> 5;
    const float4* r4 = (const float4*)(g_S + (size_t)row * Nn);
    unsigned key[16];
#pragma unroll
    for (int i = 0; i < 4; i++) {
        float4 v = r4[t + i * 256];
        float vv[4] = {v.x, v.y, v.z, v.w};
#pragma unroll
        for (int j = 0; j < 4; j++) {
            unsigned u = __float_as_uint(vv[j]);
            key[i * 4 + j] = (u & 0x80000000u) ? ~u : (u | 0x80000000u);
        }
    }
    __shared__ int hist[256];
    __shared__ int wsum[8];
    __shared__ unsigned sPrefix;
    __shared__ int sRemain;
    __shared__ int sOutc, sEqc;
    __shared__ int eqbuf[64];
    if (t == 0) { sRemain = Kk; sOutc = 0; sEqc = 0; }
    unsigned prefix = 0;
#pragma unroll
    for (int pass = 0; pass < 4; pass++) {
        int shift = 24 - 8 * pass;
        hist[t] = 0;
        __syncthreads();
#pragma unroll
        for (int i = 0; i < 16; i++) {
            bool act = (pass == 0) || ((key[i] >> (shift + 8)) == prefix);
            if (act) atomicAdd(&hist[(key[i] >> shift) & 255], 1);
        }
        __syncthreads();
        int h = hist[t];
        int remain = sRemain;
        int v = h;
#pragma unroll
        for (int off = 1; off < 32; off <<= 1) {
            int u = __shfl_down_sync(0xffffffffu, v, off);
            if (lane + off < 32) v += u;
        }
        if (lane == 0) wsum[wid] = v;
        __syncthreads();
        int tail = 0;
#pragma unroll
        for (int w2 = 0; w2 < 8; w2++)
            if (w2 > wid) tail += wsum[w2];
        int suf = v + tail;
        if (suf >= remain && suf - h < remain) {
            sPrefix = (prefix << 8) | (unsigned)t;
            sRemain = remain - (suf - h);
        }
        __syncthreads();
        prefix = sPrefix;
    }
    unsigned T = prefix;
    int remain = sRemain;
    int* outp = g_idxb + (size_t)row * Kk;
#pragma unroll
    for (int i = 0; i < 16; i++) {
        int idx = (t + (i >> 2) * 256) * 4 + (i & 3);
        if (key[i] > T) {
            int p = atomicAdd(&sOutc, 1);
            outp[p] = idx;
        } else if (key[i] == T) {
            int e = atomicAdd(&sEqc, 1);
            if (e < 64) eqbuf[e] = idx;
        }
    }
    __syncthreads();
    if (t == 0) {
        int base = sOutc;
        int ec = sEqc < 64 ? sEqc : 64;
        for (int rnd = 0; rnd < remain; rnd++) {
            int bi = 1 << 30, bp = -1;
            for (int e = 0; e < ec; e++)
                if (eqbuf[e] < bi) { bi = eqbuf[e]; bp = e; }
            outp[base + rnd] = bi;
            eqbuf[bp] = 1 << 30;
        }
    }
}

// -------- A = W[:, :64] . x, Bv = W[:, 64:128] . x  ------------------------
__global__ __launch_bounds__(256) void k_projAB(const float* __restrict__ wl) {
    __shared__ float sF[64][64];
    int bn0 = blockIdx.x * 64;
    int t = threadIdx.x;
    for (int e = t; e < 4096; e += 256) {
        int n = e >> 6, d = e & 63;
        sF[n][d] = g_ft[(size_t)(bn0 + n) * Dd + d];
    }
    __syncthreads();
    int half = t >> 7, o = t & 127;
    float wr[64];
#pragma unroll
    for (int d = 0; d < 64; d++) wr[d] = wl[o * 129 + half * 64 + d];
    float* dst = half ? g_Bloc : g_Aloc;
    for (int nn = 0; nn < 64; nn++) {
        float acc = 0.f;
#pragma unroll
        for (int d = 0; d < 64; d++) acc = fmaf(wr[d], sF[nn][d], acc);
        dst[(size_t)(bn0 + nn) * Oo + o] = acc;
    }
}

// --- gather neighbors, dist, y = A + Bv[j] + w_last*dist; max/min + stats --
__global__ __launch_bounds__(128) void k_intra(const float* __restrict__ wl) {
    __shared__ float sCen[64];
    __shared__ float sPart[16][8];
    __shared__ float sDist[16];
    __shared__ int sJ[16];
    int t = threadIdx.x;
    float wlast = wl[t * 129 + 128];
    float accS = 0.f, accQ = 0.f;
    for (int g = 0; g < 32; g++) {
        int bn = blockIdx.x * 32 + g;
        int b = bn >> 12;
        if (t < 64) sCen[t] = g_ft[(size_t)bn * Dd + t];
        __syncthreads();
        {
            int k = t >> 3, dg = t & 7;
            int j = g_idxb[(size_t)bn * Kk + k];
            const float* nr = g_ft + ((size_t)b * Nn + j) * Dd + dg * 8;
            float p = 0.f;
#pragma unroll
            for (int d = 0; d < 8; d++) {
                float df = nr[d] - sCen[dg * 8 + d];
                p = fmaf(df, df, p);
            }
            sPart[k][dg] = p;
            if (dg == 0) sJ[k] = j;
        }
        __syncthreads();
        if (t < 16) {
            float s = 0.f;
#pragma unroll
            for (int d = 0; d < 8; d++) s += sPart[t][d];
            sDist[t] = sqrtf(s);
        }
        __syncthreads();
        float a = g_Aloc[(size_t)bn * Oo + t];
        float mx = NEGINF, mn = -NEGINF;
#pragma unroll
        for (int kk = 0; kk < Kk; kk++) {
            int jj = sJ[kk];
            float y = a + g_Bloc[((size_t)b * Nn + jj) * Oo + t] + wlast * sDist[kk];
            mx = fmaxf(mx, y);
            mn = fminf(mn, y);
            accS += y;
            accQ = fmaf(y, y, accQ);
        }
        g_ymax[(size_t)bn * Oo + t] = mx;
        g_ymin[(size_t)bn * Oo + t] = mn;
        __syncthreads();
    }
    g_p1s[(size_t)blockIdx.x * Oo + t] = accS;
    g_p1q[(size_t)blockIdx.x * Oo + t] = accQ;
}

// ---------------- q,k,v projections (coalesced writes) ---------------------
__global__ __launch_bounds__(256) void k_qkv(const float* __restrict__ f,
    const float* __restrict__ wq, const float* __restrict__ bq,
    const float* __restrict__ wk, const float* __restrict__ bk,
    const float* __restrict__ wv, const float* __restrict__ bv) {
    extern __shared__ float qsm[];
    float* sF = qsm;                 // [64][65]
    float* sW = qsm + 64 * 65;       // [192][64]
    float* sBias = sW + 192 * 64;    // [192]
    int t = threadIdx.x, lane = t & 31, wid = t >> 5;
    int b = blockIdx.y, n0 = blockIdx.x * 64;
    const float* fb = f + (size_t)b * Dd * Nn;
    for (int e = t; e < 64 * 64; e += 256) {
        int d = e >> 6, nn = e & 63;
        sF[d * 65 + nn] = fb[(size_t)d * Nn + n0 + nn];
    }
    for (int e = t; e < 192 * 64; e += 256) {
        int r = e >> 6, d = e & 63;
        const float* W = r < 64 ? wq : (r < 128 ? wk : wv);
        sW[e] = W[(r & 63) * 64 + d];
    }
    if (t < 192) sBias[t] = t < 64 ? bq[t] : (t < 128 ? bk[t - 64] : bv[t - 128]);
    __syncthreads();
#pragma unroll 4
    for (int j = 0; j < 24; j++) {
        int r = wid + 8 * j;
        const float* wr = sW + r * 64;
        float a0 = sBias[r], a1 = a0;
#pragma unroll 16
        for (int d = 0; d < 64; d++) {
            float w = wr[d];
            a0 = fmaf(w, sF[d * 65 + lane], a0);
            a1 = fmaf(w, sF[d * 65 + lane + 32], a1);
        }
        int mat = r >> 6, o = r & 63;
        float* outp = (mat == 0 ? g_q : (mat == 1 ? g_k : g_v)) + ((size_t)b * Dd + o) * Nn + n0;
        outp[lane] = a0;
        outp[lane + 32] = a1;
    }
}

// ----- flash attention: 64 q-rows per CTA, 128 threads (4 warps) -----------
// grid (64, Bx) = 256 CTAs: all SMs covered, multi-CTA/SM overlap.
__global__ __launch_bounds__(128) void k_flash() {
    extern __shared__ uint32_t fsm[];
    uint32_t* sK = fsm;                    // 64*72
    uint32_t* sP = fsm + 64 * 72;          // 64*72
    uint32_t* sV = fsm + 2 * 64 * 72;      // 64*72
    float* sQ = (float*)fsm;               // prologue only: [64 d][72], 64 m
    float* sO = (float*)fsm;               // epilogue only: [64 d][65], 64 m
    int t = threadIdx.x, lane = t & 31, wid = t >> 5;   // wid 0..3
    int gid = lane >> 2, ctg = lane & 3;
    int b = blockIdx.y, m0 = blockIdx.x * 64;
    int mwb = wid * 16;
    const float* qb = g_q + (size_t)b * Dd * Nn;
    const float* kb_ = g_k + (size_t)b * Dd * Nn;
    const float* vb = g_v + (size_t)b * Dd * Nn;

    // prologue: stage 64-row Q tile, extract scaled A-fragments
#pragma unroll
    for (int i = 0; i < 32; i++) {
        int e = t + i * 128;
        int d = e >> 6, m = e & 63;
        sQ[d * 72 + m] = qb[(size_t)d * Nn + m0 + m] * 0.125f;
    }
    __syncthreads();
    uint32_t qf[8][4];
#pragma unroll
    for (int ks = 0; ks < 8; ks++) {
        int kb = ks * 8 + ctg;
        int mb = mwb + gid;
        qf[ks][0] = tf32one(sQ[kb * 72 + mb]);
        qf[ks][1] = tf32one(sQ[kb * 72 + mb + 8]);
        qf[ks][2] = tf32one(sQ[(kb + 4) * 72 + mb]);
        qf[ks][3] = tf32one(sQ[(kb + 4) * 72 + mb + 8]);
    }
    __syncthreads();

    float mo0 = NEGINF, mo1 = NEGINF, l0 = 0.f, l1 = 0.f;
    float oacc[8][4] = {};
    for (int nc = 0; nc < 64; nc++) {
        int n0 = nc * 64;
        __syncthreads();
#pragma unroll
        for (int i = 0; i < 32; i++) {
            int e = t + i * 128;
            int d = e >> 6, nn = e & 63;
            sK[d * 72 + nn] = tf32one(kb_[(size_t)d * Nn + n0 + nn]);
            sV[d * 72 + nn] = tf32one(vb[(size_t)d * Nn + n0 + nn]);
        }
        __syncthreads();
        float c[8][4] = {};
#pragma unroll
        for (int ks = 0; ks < 8; ks++) {
            int kb = ks * 8 + ctg;
#pragma unroll
            for (int nf = 0; nf < 8; nf++) {
                int nb = nf * 8 + gid;
                uint32_t bb[2];
                bb[0] = sK[kb * 72 + nb];
                bb[1] = sK[(kb + 4) * 72 + nb];
                mma_m16n8k8(c[nf], qf[ks], bb);
            }
        }
        float tm0 = NEGINF, tm1 = NEGINF;
#pragma unroll
        for (int nf = 0; nf < 8; nf++) {
            tm0 = fmaxf(tm0, fmaxf(c[nf][0], c[nf][1]));
            tm1 = fmaxf(tm1, fmaxf(c[nf][2], c[nf][3]));
        }
#pragma unroll
        for (int off = 1; off <= 2; off <<= 1) {
            tm0 = fmaxf(tm0, __shfl_xor_sync(0xffffffffu, tm0, off));
            tm1 = fmaxf(tm1, __shfl_xor_sync(0xffffffffu, tm1, off));
        }
        float mn0 = fmaxf(mo0, tm0), mn1 = fmaxf(mo1, tm1);
        float s0 = __expf(mo0 - mn0), s1 = __expf(mo1 - mn1);
        float sum0 = 0.f, sum1 = 0.f;
#pragma unroll
        for (int nf = 0; nf < 8; nf++) {
            float p00 = __expf(c[nf][0] - mn0);
            float p01 = __expf(c[nf][1] - mn0);
            float p10 = __expf(c[nf][2] - mn1);
            float p11 = __expf(c[nf][3] - mn1);
            sum0 += p00 + p01;
            sum1 += p10 + p11;
            int nl = nf * 8 + 2 * ctg;
            sP[(mwb + gid) * 72 + nl]     = tf32one(p00);
            sP[(mwb + gid) * 72 + nl + 1] = tf32one(p01);
            sP[(mwb + gid + 8) * 72 + nl]     = tf32one(p10);
            sP[(mwb + gid + 8) * 72 + nl + 1] = tf32one(p11);
        }
#pragma unroll
        for (int off = 1; off <= 2; off <<= 1) {
            sum0 += __shfl_xor_sync(0xffffffffu, sum0, off);
            sum1 += __shfl_xor_sync(0xffffffffu, sum1, off);
        }
        l0 = l0 * s0 + sum0;
        l1 = l1 * s1 + sum1;
#pragma unroll
        for (int nf = 0; nf < 8; nf++) {
            oacc[nf][0] *= s0; oacc[nf][1] *= s0;
            oacc[nf][2] *= s1; oacc[nf][3] *= s1;
        }
        __syncwarp();
#pragma unroll
        for (int ks = 0; ks < 8; ks++) {
            int kb = ks * 8 + ctg;
            uint32_t a[4];
            a[0] = sP[(mwb + gid) * 72 + kb];
            a[1] = sP[(mwb + gid + 8) * 72 + kb];
            a[2] = sP[(mwb + gid) * 72 + kb + 4];
            a[3] = sP[(mwb + gid + 8) * 72 + kb + 4];
#pragma unroll
            for (int nf = 0; nf < 8; nf++) {
                int nb = nf * 8 + gid;
                uint32_t bb[2];
                bb[0] = sV[nb * 72 + kb];
                bb[1] = sV[nb * 72 + kb + 4];
                mma_m16n8k8(oacc[nf], a, bb);
            }
        }
        mo0 = mn0; mo1 = mn1;
    }
    float is0 = 1.0f / l0, is1 = 1.0f / l1;
    __syncthreads();
#pragma unroll
    for (int nf = 0; nf < 8; nf++) {
        int d0 = nf * 8 + 2 * ctg;
        int ml = mwb + gid;
        sO[d0 * 65 + ml]           = oacc[nf][0] * is0;
        sO[(d0 + 1) * 65 + ml]     = oacc[nf][1] * is0;
        sO[d0 * 65 + ml + 8]       = oacc[nf][2] * is1;
        sO[(d0 + 1) * 65 + ml + 8] = oacc[nf][3] * is1;
    }
    __syncthreads();
#pragma unroll
    for (int i = 0; i < 32; i++) {
        int e = t + i * 128;
        int d = e >> 6, m = e & 63;
        g_fgt[((size_t)b * Dd + d) * Nn + m0 + m] = sO[d * 65 + m];
    }
}

// ------------------- inter pre-bn: z2 = w_sem . fgt ------------------------
__global__ __launch_bounds__(128) void k_inter(const float* __restrict__ wsem) {
    __shared__ float sF[64][64];
    int b = blockIdx.y, n0 = blockIdx.x * 64, t = threadIdx.x;
    const float* fb = g_fgt + (size_t)b * Dd * Nn;
    for (int e = t; e < 4096; e += 128) {
        int d = e >> 6, nn = e & 63;
        sF[d][nn] = fb[(size_t)d * Nn + n0 + nn];
    }
    __syncthreads();
    float wr[64];
#pragma unroll
    for (int d = 0; d < 64; d++) wr[d] = wsem[t * 64 + d];
    float aS = 0.f, aQ = 0.f;
    for (int nn = 0; nn < 64; nn++) {
        float acc = 0.f;
#pragma unroll
        for (int d = 0; d < 64; d++) acc = fmaf(wr[d], sF[d][nn], acc);
        g_z2[((size_t)b * Nn + n0 + nn) * Oo + t] = acc;
        aS += acc;
        aQ = fmaf(acc, acc, aQ);
    }
    int blk = blockIdx.y * gridDim.x + blockIdx.x;
    g_p2s[(size_t)blk * Oo + t] = aS;
    g_p2q[(size_t)blk * Oo + t] = aQ;
}

// --------- bn stat finalize ------------------------------------------------
__global__ void k_bnstats(int which, int nblk, float invcnt,
                          const float* __restrict__ gamma, const float* __restrict__ beta) {
    int o = threadIdx.x;
    const float *ps, *pq;
    float *sc, *sh;
    if (which == 1) { ps = g_p1s; pq = g_p1q; sc = g_sc1; sh = g_sh1; }
    else if (which == 2) { ps = g_p2s; pq = g_p2q; sc = g_sc2; sh = g_sh2; }
    else { ps = g_p3s; pq = g_p3q; sc = g_sc3; sh = g_sh3; }
    float s = 0.f, q = 0.f;
    for (int i = 0; i < nblk; i++) {
        s += ps[(size_t)i * Oo + o];
        q += pq[(size_t)i * Oo + o];
    }
    float mean = s * invcnt;
    float var = q * invcnt - mean * mean;
    float scl = gamma[o] / sqrtf(var + 1e-5f);
    sc[o] = scl;
    sh[o] = beta[o] - mean * scl;
}

// --------- z3 = w_full . [lrelu(bn1(intra)); lrelu(bn2(inter))] ------------
__global__ __launch_bounds__(128) void k_z3(const float* __restrict__ wfull) {
    __shared__ float sC[16][256];
    __shared__ float sW[32][129];
    int bn0 = blockIdx.x * 16, t = threadIdx.x;
    for (int e = t; e < 16 * 256; e += 128) {
        int n = e >> 8, c = e & 255;
        int bn = bn0 + n;
        float pre;
        if (c < 128) {
            float s1 = g_sc1[c];
            float ym = (s1 >= 0.f) ? g_ymax[(size_t)bn * Oo + c] : g_ymin[(size_t)bn * Oo + c];
            pre = fmaf(s1, ym, g_sh1[c]);
        } else {
            int o = c - 128;
            pre = fmaf(g_sc2[o], g_z2[(size_t)bn * Oo + o], g_sh2[o]);
        }
        sC[n][c] = pre >= 0.f ? pre : NEG * pre;
    }
    float acc[16] = {};
    for (int ch = 0; ch < 8; ch++) {
        __syncthreads();
        for (int e = t; e < 32 * 128; e += 128) {
            int o = e >> 5, c = e & 31;
            sW[c][o] = wfull[(size_t)o * 256 + ch * 32 + c];
        }
        __syncthreads();
#pragma unroll 4
        for (int c = 0; c < 32; c++) {
            float w = sW[c][t];
            int cg = ch * 32 + c;
#pragma unroll
            for (int n = 0; n < 16; n++) acc[n] = fmaf(w, sC[n][cg], acc[n]);
        }
    }
    float aS = 0.f, aQ = 0.f;
#pragma unroll
    for (int n = 0; n < 16; n++) {
        float z = acc[n];
        g_z3[(size_t)(bn0 + n) * Oo + t] = z;
        aS += z;
        aQ = fmaf(z, z, aQ);
    }
    g_p3s[(size_t)blockIdx.x * Oo + t] = aS;
    g_p3q[(size_t)blockIdx.x * Oo + t] = aQ;
}

// --------- out[b,o,n] = lrelu(bn3(z3)) with transpose ----------------------
__global__ __launch_bounds__(256) void k_out(float* __restrict__ out) {
    __shared__ float tile[32][33];
    int b = blockIdx.z, o0 = blockIdx.y * 32, n0 = blockIdx.x * 32;
    int tx = threadIdx.x & 31, ty = threadIdx.x >> 5;
    float scl = g_sc3[o0 + tx], sh = g_sh3[o0 + tx];
#pragma unroll
    for (int i = 0; i < 4; i++) {
        int n = n0 + ty + i * 8;
        float v = fmaf(scl, g_z3[((size_t)b * Nn + n) * Oo + o0 + tx], sh);
        tile[ty + i * 8][tx] = v >= 0.f ? v : NEG * v;
    }
    __syncthreads();
#pragma unroll
    for (int i = 0; i < 4; i++) {
        int o = o0 + ty + i * 8;
        out[((size_t)b * Oo + o) * Nn + n0 + tx] = tile[tx][ty + i * 8];
    }
}

// ---------------------------------------------------------------------------
extern "C" void kernel_launch(void* const* d_in, const int* in_sizes, int n_in,
                              void* d_out, int out_size) {
    const float* f       = (const float*)d_in[0];
    const float* w_local = (const float*)d_in[1];
    const float* g_local = (const float*)d_in[2];
    const float* b_local = (const float*)d_in[3];
    const float* w_sem   = (const float*)d_in[4];
    const float* g_sem   = (const float*)d_in[5];
    const float* b_sem   = (const float*)d_in[6];
    const float* w_full  = (const float*)d_in[7];
    const float* g_full  = (const float*)d_in[8];
    const float* b_full  = (const float*)d_in[9];
    const float* wq = (const float*)d_in[10];
    const float* bq = (const float*)d_in[11];
    const float* wk = (const float*)d_in[12];
    const float* bk = (const float*)d_in[13];
    const float* wv = (const float*)d_in[14];
    const float* bv = (const float*)d_in[15];
    float* out = (float*)d_out;

    const int MM_SMEM = 128 * KST * 4;                 // 69632 bytes
    const int FL_SMEM = 3 * 64 * 72 * 4;               // 55296 bytes
    const int QK_SMEM = (64 * 65 + 192 * 64 + 192) * 4; // 66560 bytes
    cudaFuncSetAttribute(k_mm, cudaFuncAttributeMaxDynamicSharedMemorySize, MM_SMEM);
    cudaFuncSetAttribute(k_flash, cudaFuncAttributeMaxDynamicSharedMemorySize, FL_SMEM);
    cudaFuncSetAttribute(k_qkv, cudaFuncAttributeMaxDynamicSharedMemorySize, QK_SMEM);

    k_xx<<<64, 256>>>(f);
    k_tr<<<dim3(Nn / 32, Dd / 32, Bx), 256>>>(f);
    k_mm<<<dim3(32, 32, Bx), 256, MM_SMEM>>>(f);
    k_topk<<<Bx * Nn, 256>>>();
    k_projAB<<<Bx * Nn / 64, 256>>>(w_local);
    k_intra<<<Bx * Nn / 32, 128>>>(w_local);
    k_bnstats<<<1, 128>>>(1, 512, 1.0f / (Bx * Nn * Kk), g_local, b_local);
    k_qkv<<<dim3(64, Bx), 256, QK_SMEM>>>(f, wq, bq, wk, bk, wv, bv);
    k_flash<<<dim3(64, Bx), 128, FL_SMEM>>>();
    k_inter<<<dim3(64, Bx), 128>>>(w_sem);
    k_bnstats<<<1, 128>>>(2, 256, 1.0f / (Bx * Nn), g_sem, b_sem);
    k_z3<<<Bx * Nn / 16, 128>>>(w_full);
    k_bnstats<<<1, 128>>>(3, 1024, 1.0f / (Bx * Nn), g_full, b_full);
    k_out<<<dim3(Nn / 32, Oo / 32, Bx), 256>>>(out);
}

// round 17
// speedup vs baseline: 1.2876x; 1.0374x over previous
#include <cuda_runtime.h>
#include <math.h>
#include <stdint.h>

#define Bx 4
#define Dd 64
#define Nn 4096
#define Oo 128
#define Kk 16
#define NEG 0.01f
#define NEGINF (-1.0e30f)

// ------------------------- static device scratch ---------------------------
__device__ float g_S[(size_t)Bx * Nn * Nn];
__device__ float g_xx[Bx * Nn];
__device__ float g_ft[Bx * Nn * Dd];
__device__ float g_q[Bx * Dd * Nn];
__device__ float g_k[Bx * Dd * Nn];
__device__ float g_v[Bx * Dd * Nn];
__device__ float g_Aloc[(size_t)Bx * Nn * Oo];
__device__ float g_Bloc[(size_t)Bx * Nn * Oo];
__device__ int   g_idxb[Bx * Nn * Kk];
__device__ float g_ymax[(size_t)Bx * Nn * Oo];
__device__ float g_ymin[(size_t)Bx * Nn * Oo];
__device__ float g_z2[(size_t)Bx * Nn * Oo];
__device__ float g_z3[(size_t)Bx * Nn * Oo];
__device__ float g_fgt[Bx * Dd * Nn];
__device__ float g_p1s[1024 * Oo], g_p1q[1024 * Oo];
__device__ float g_p2s[256 * Oo], g_p2q[256 * Oo];
__device__ float g_p3s[1024 * Oo], g_p3q[1024 * Oo];
__device__ float g_sc1[Oo], g_sh1[Oo], g_sc2[Oo], g_sh2[Oo], g_sc3[Oo], g_sh3[Oo];

// ------------------------- helpers -----------------------------------------
__device__ __forceinline__ void tf32split_u(float x, uint32_t& hi, uint32_t& lo) {
    asm("cvt.rna.tf32.f32 %0, %1;" : "=r"(hi) : "f"(x));
    float l = x - __uint_as_float(hi);
    asm("cvt.rna.tf32.f32 %0, %1;" : "=r"(lo) : "f"(l));
}
__device__ __forceinline__ uint32_t tf32one(float x) {
    uint32_t h;
    asm("cvt.rna.tf32.f32 %0, %1;" : "=r"(h) : "f"(x));
    return h;
}
__device__ __forceinline__ void mma_m16n8k8(float* c, const uint32_t* a, const uint32_t* b) {
    asm volatile(
        "mma.sync.aligned.m16n8k8.row.col.f32.tf32.tf32.f32 "
        "{%0,%1,%2,%3}, {%4,%5,%6,%7}, {%8,%9}, {%0,%1,%2,%3};"
        : "+f"(c[0]), "+f"(c[1]), "+f"(c[2]), "+f"(c[3])
        : "r"(a[0]), "r"(a[1]), "r"(a[2]), "r"(a[3]), "r"(b[0]), "r"(b[1]));
}

// ------------------------- xx[b,n] = sum_d f^2 -----------------------------
__global__ void k_xx(const float* __restrict__ f) {
    int id = blockIdx.x * 256 + threadIdx.x;
    int b = id >> 12;
    int n = id & (Nn - 1);
    const float* fb = f + (size_t)b * Dd * Nn + n;
    float s = 0.f;
#pragma unroll
    for (int d = 0; d < Dd; d++) {
        float v = fb[(size_t)d * Nn];
        s = fmaf(v, v, s);
    }
    g_xx[id] = s;
}

// ------------------------- transpose f -> (B,N,D) --------------------------
__global__ __launch_bounds__(256) void k_tr(const float* __restrict__ f) {
    __shared__ float tile[32][33];
    int b = blockIdx.z, d0 = blockIdx.y * 32, n0 = blockIdx.x * 32;
    int tx = threadIdx.x & 31, ty = threadIdx.x >> 5;
#pragma unroll
    for (int i = 0; i < 4; i++)
        tile[ty + i * 8][tx] = f[((size_t)b * Dd + d0 + ty + i * 8) * Nn + n0 + tx];
    __syncthreads();
#pragma unroll
    for (int i = 0; i < 4; i++)
        g_ft[((size_t)b * Nn + n0 + ty + i * 8) * Dd + d0 + tx] = tile[tx][ty + i * 8];
}

// -------- warp-MMA tf32 GEMM: pd (3-term split) -> g_S ---------------------
#define KST 136
__global__ __launch_bounds__(256, 2) void k_mm(const float* __restrict__ f) {
    extern __shared__ uint32_t dsm[];
    __shared__ float sXM[128], sXN[128];
    uint32_t* sAh = dsm;
    uint32_t* sAl = dsm + 32 * KST;
    uint32_t* sBh = dsm + 64 * KST;
    uint32_t* sBl = dsm + 96 * KST;
    int t = threadIdx.x, lane = t & 31, wid = t >> 5;
    int wm = wid & 3, wn = wid >> 2;
    int gid = lane >> 2, ctg = lane & 3;
    int b = blockIdx.z, m0 = blockIdx.y * 128, n0 = blockIdx.x * 128;
    const float* Ap = f + (size_t)b * Dd * Nn;
    if (t < 128) sXM[t] = g_xx[b * Nn + m0 + t];
    else sXN[t - 128] = g_xx[b * Nn + n0 + t - 128];
    float acc[2][8][4] = {};
#pragma unroll
    for (int kc = 0; kc < 2; kc++) {
        int kc0 = kc * 32;
        __syncthreads();
#pragma unroll
        for (int i = 0; i < 16; i++) {
            int e = t + i * 256;
            int d = e >> 7, m = e & 127;
            float a  = Ap[(size_t)(kc0 + d) * Nn + m0 + m];
            float bb = Ap[(size_t)(kc0 + d) * Nn + n0 + m];
            uint32_t hi, lo;
            tf32split_u(a, hi, lo);  sAh[d * KST + m] = hi; sAl[d * KST + m] = lo;
            tf32split_u(bb, hi, lo); sBh[d * KST + m] = hi; sBl[d * KST + m] = lo;
        }
        __syncthreads();
#pragma unroll
        for (int ks = 0; ks < 4; ks++) {
            int kb = ks * 8 + ctg;
            uint32_t ah[2][4], al[2][4];
#pragma unroll
            for (int mi = 0; mi < 2; mi++) {
                int mb = wm * 32 + mi * 16 + gid;
                ah[mi][0] = sAh[kb * KST + mb];
                ah[mi][1] = sAh[kb * KST + mb + 8];
                ah[mi][2] = sAh[(kb + 4) * KST + mb];
                ah[mi][3] = sAh[(kb + 4) * KST + mb + 8];
                al[mi][0] = sAl[kb * KST + mb];
                al[mi][1] = sAl[kb * KST + mb + 8];
                al[mi][2] = sAl[(kb + 4) * KST + mb];
                al[mi][3] = sAl[(kb + 4) * KST + mb + 8];
            }
#pragma unroll
            for (int nf = 0; nf < 8; nf++) {
                int nb = wn * 64 + nf * 8 + gid;
                uint32_t bh[2], bl[2];
                bh[0] = sBh[kb * KST + nb];
                bh[1] = sBh[(kb + 4) * KST + nb];
                bl[0] = sBl[kb * KST + nb];
                bl[1] = sBl[(kb + 4) * KST + nb];
#pragma unroll
                for (int mi = 0; mi < 2; mi++) {
                    mma_m16n8k8(acc[mi][nf], ah[mi], bh);
                    mma_m16n8k8(acc[mi][nf], ah[mi], bl);
                    mma_m16n8k8(acc[mi][nf], al[mi], bh);
                }
            }
        }
    }
    float* outp = g_S + (size_t)b * Nn * Nn;
#pragma unroll
    for (int mi = 0; mi < 2; mi++) {
#pragma unroll
        for (int nf = 0; nf < 8; nf++) {
            float* c = acc[mi][nf];
            int ml = wm * 32 + mi * 16 + gid;
            int nl = wn * 64 + nf * 8 + 2 * ctg;
            float2 v0 = { 2.f * c[0] - sXM[ml] - sXN[nl],
                          2.f * c[1] - sXM[ml] - sXN[nl + 1] };
            float2 v1 = { 2.f * c[2] - sXM[ml + 8] - sXN[nl],
                          2.f * c[3] - sXM[ml + 8] - sXN[nl + 1] };
            *(float2*)&outp[(size_t)(m0 + ml) * Nn + n0 + nl] = v0;
            *(float2*)&outp[(size_t)(m0 + ml + 8) * Nn + n0 + nl] = v1;
        }
    }
}

// -------------- top-16 per row via 4-pass radix select ---------------------
__global__ __launch_bounds__(256) void k_topk() {
    int row = blockIdx.x;
    int t = threadIdx.x, lane = t & 31, wid = t >> 5;
    const float4* r4 = (const float4*)(g_S + (size_t)row * Nn);
    unsigned key[16];
#pragma unroll
    for (int i = 0; i < 4; i++) {
        float4 v = r4[t + i * 256];
        float vv[4] = {v.x, v.y, v.z, v.w};
#pragma unroll
        for (int j = 0; j < 4; j++) {
            unsigned u = __float_as_uint(vv[j]);
            key[i * 4 + j] = (u & 0x80000000u) ? ~u : (u | 0x80000000u);
        }
    }
    __shared__ int hist[256];
    __shared__ int wsum[8];
    __shared__ unsigned sPrefix;
    __shared__ int sRemain;
    __shared__ int sOutc, sEqc;
    __shared__ int eqbuf[64];
    if (t == 0) { sRemain = Kk; sOutc = 0; sEqc = 0; }
    unsigned prefix = 0;
#pragma unroll
    for (int pass = 0; pass < 4; pass++) {
        int shift = 24 - 8 * pass;
        hist[t] = 0;
        __syncthreads();
#pragma unroll
        for (int i = 0; i < 16; i++) {
            bool act = (pass == 0) || ((key[i] >> (shift + 8)) == prefix);
            if (act) atomicAdd(&hist[(key[i] >> shift) & 255], 1);
        }
        __syncthreads();
        int h = hist[t];
        int remain = sRemain;
        int v = h;
#pragma unroll
        for (int off = 1; off < 32; off <<= 1) {
            int u = __shfl_down_sync(0xffffffffu, v, off);
            if (lane + off < 32) v += u;
        }
        if (lane == 0) wsum[wid] = v;
        __syncthreads();
        int tail = 0;
#pragma unroll
        for (int w2 = 0; w2 < 8; w2++)
            if (w2 > wid) tail += wsum[w2];
        int suf = v + tail;
        if (suf >= remain && suf - h < remain) {
            sPrefix = (prefix << 8) | (unsigned)t;
            sRemain = remain - (suf - h);
        }
        __syncthreads();
        prefix = sPrefix;
    }
    unsigned T = prefix;
    int remain = sRemain;
    int* outp = g_idxb + (size_t)row * Kk;
#pragma unroll
    for (int i = 0; i < 16; i++) {
        int idx = (t + (i >> 2) * 256) * 4 + (i & 3);
        if (key[i] > T) {
            int p = atomicAdd(&sOutc, 1);
            outp[p] = idx;
        } else if (key[i] == T) {
            int e = atomicAdd(&sEqc, 1);
            if (e < 64) eqbuf[e] = idx;
        }
    }
    __syncthreads();
    if (t == 0) {
        int base = sOutc;
        int ec = sEqc < 64 ? sEqc : 64;
        for (int rnd = 0; rnd < remain; rnd++) {
            int bi = 1 << 30, bp = -1;
            for (int e = 0; e < ec; e++)
                if (eqbuf[e] < bi) { bi = eqbuf[e]; bp = e; }
            outp[base + rnd] = bi;
            eqbuf[bp] = 1 << 30;
        }
    }
}

// -------- A = W[:, :64] . x, Bv = W[:, 64:128] . x  ------------------------
__global__ __launch_bounds__(256) void k_projAB(const float* __restrict__ wl) {
    __shared__ float sF[64][64];
    int bn0 = blockIdx.x * 64;
    int t = threadIdx.x;
    for (int e = t; e < 4096; e += 256) {
        int n = e >> 6, d = e & 63;
        sF[n][d] = g_ft[(size_t)(bn0 + n) * Dd + d];
    }
    __syncthreads();
    int half = t >> 7, o = t & 127;
    float wr[64];
#pragma unroll
    for (int d = 0; d < 64; d++) wr[d] = wl[o * 129 + half * 64 + d];
    float* dst = half ? g_Bloc : g_Aloc;
    for (int nn = 0; nn < 64; nn++) {
        float acc = 0.f;
#pragma unroll
        for (int d = 0; d < 64; d++) acc = fmaf(wr[d], sF[nn][d], acc);
        dst[(size_t)(bn0 + nn) * Oo + o] = acc;
    }
}

// --- gather neighbors, dist, y = A + Bv[j] + w_last*dist; max/min + stats --
// 256 threads, 2 points concurrently (s = t>>7); shuffle-tree distance.
__global__ __launch_bounds__(256) void k_intra(const float* __restrict__ wl) {
    __shared__ float sCen[2][64];
    __shared__ float sDist[2][16];
    __shared__ int sJ[2][16];
    int t = threadIdx.x;
    int s = t >> 7, tid = t & 127;
    float wlast = wl[tid * 129 + 128];
    float accS = 0.f, accQ = 0.f;
    for (int g = 0; g < 16; g++) {
        int bn = blockIdx.x * 32 + g * 2 + s;
        int b = bn >> 12;
        if (tid < 64) sCen[s][tid] = g_ft[(size_t)bn * Dd + tid];
        __syncthreads();
        {
            int k = tid >> 3, dg = tid & 7;
            int j = g_idxb[(size_t)bn * Kk + k];
            const float* nr = g_ft + ((size_t)b * Nn + j) * Dd + dg * 8;
            float p = 0.f;
#pragma unroll
            for (int d = 0; d < 8; d++) {
                float df = nr[d] - sCen[s][dg * 8 + d];
                p = fmaf(df, df, p);
            }
            // 8-lane shuffle tree (lanes k*8..k*8+7 contiguous in warp)
            p += __shfl_down_sync(0xffffffffu, p, 4, 8);
            p += __shfl_down_sync(0xffffffffu, p, 2, 8);
            p += __shfl_down_sync(0xffffffffu, p, 1, 8);
            if (dg == 0) {
                sDist[s][k] = sqrtf(p);
                sJ[s][k] = j;
            }
        }
        __syncthreads();
        float a = g_Aloc[(size_t)bn * Oo + tid];
        float mx = NEGINF, mn = -NEGINF;
#pragma unroll
        for (int kk = 0; kk < Kk; kk++) {
            int jj = sJ[s][kk];
            float y = a + g_Bloc[((size_t)b * Nn + jj) * Oo + tid] + wlast * sDist[s][kk];
            mx = fmaxf(mx, y);
            mn = fminf(mn, y);
            accS += y;
            accQ = fmaf(y, y, accQ);
        }
        g_ymax[(size_t)bn * Oo + tid] = mx;
        g_ymin[(size_t)bn * Oo + tid] = mn;
        __syncthreads();
    }
    g_p1s[(size_t)(blockIdx.x * 2 + s) * Oo + tid] = accS;
    g_p1q[(size_t)(blockIdx.x * 2 + s) * Oo + tid] = accQ;
}

// ---------------- q,k,v projections (coalesced writes) ---------------------
__global__ __launch_bounds__(256) void k_qkv(const float* __restrict__ f,
    const float* __restrict__ wq, const float* __restrict__ bq,
    const float* __restrict__ wk, const float* __restrict__ bk,
    const float* __restrict__ wv, const float* __restrict__ bv) {
    extern __shared__ float qsm[];
    float* sF = qsm;                 // [64][65]
    float* sW = qsm + 64 * 65;       // [192][64]
    float* sBias = sW + 192 * 64;    // [192]
    int t = threadIdx.x, lane = t & 31, wid = t >> 5;
    int b = blockIdx.y, n0 = blockIdx.x * 64;
    const float* fb = f + (size_t)b * Dd * Nn;
    for (int e = t; e < 64 * 64; e += 256) {
        int d = e >> 6, nn = e & 63;
        sF[d * 65 + nn] = fb[(size_t)d * Nn + n0 + nn];
    }
    for (int e = t; e < 192 * 64; e += 256) {
        int r = e >> 6, d = e & 63;
        const float* W = r < 64 ? wq : (r < 128 ? wk : wv);
        sW[e] = W[(r & 63) * 64 + d];
    }
    if (t < 192) sBias[t] = t < 64 ? bq[t] : (t < 128 ? bk[t - 64] : bv[t - 128]);
    __syncthreads();
#pragma unroll 4
    for (int j = 0; j < 24; j++) {
        int r = wid + 8 * j;
        const float* wr = sW + r * 64;
        float a0 = sBias[r], a1 = a0;
#pragma unroll 16
        for (int d = 0; d < 64; d++) {
            float w = wr[d];
            a0 = fmaf(w, sF[d * 65 + lane], a0);
            a1 = fmaf(w, sF[d * 65 + lane + 32], a1);
        }
        int mat = r >> 6, o = r & 63;
        float* outp = (mat == 0 ? g_q : (mat == 1 ? g_k : g_v)) + ((size_t)b * Dd + o) * Nn + n0;
        outp[lane] = a0;
        outp[lane + 32] = a1;
    }
}

// ----- flash attention: fgt = softmax(qk/8) @ v, no S materialization ------
__global__ __launch_bounds__(256) void k_flash() {
    extern __shared__ uint32_t fsm[];
    uint32_t* sK = fsm;                    // 64*72
    uint32_t* sP = fsm + 64 * 72;          // 128*72
    uint32_t* sV = fsm + 64 * 72 + 128 * 72;
    float* sQ = (float*)fsm;               // prologue only: [64][136]
    float* sO = (float*)fsm;               // epilogue only: [64][129]
    int t = threadIdx.x, lane = t & 31, wid = t >> 5;
    int gid = lane >> 2, ctg = lane & 3;
    int b = blockIdx.y, m0 = blockIdx.x * 128;
    int mwb = wid * 16;
    const float* qb = g_q + (size_t)b * Dd * Nn;
    const float* kb_ = g_k + (size_t)b * Dd * Nn;
    const float* vb = g_v + (size_t)b * Dd * Nn;

#pragma unroll
    for (int i = 0; i < 32; i++) {
        int e = t + i * 256;
        int d = e >> 7, m = e & 127;
        sQ[d * 136 + m] = qb[(size_t)d * Nn + m0 + m] * 0.125f;
    }
    __syncthreads();
    uint32_t qf[8][4];
#pragma unroll
    for (int ks = 0; ks < 8; ks++) {
        int kb = ks * 8 + ctg;
        int mb = mwb + gid;
        qf[ks][0] = tf32one(sQ[kb * 136 + mb]);
        qf[ks][1] = tf32one(sQ[kb * 136 + mb + 8]);
        qf[ks][2] = tf32one(sQ[(kb + 4) * 136 + mb]);
        qf[ks][3] = tf32one(sQ[(kb + 4) * 136 + mb + 8]);
    }

    float mo0 = NEGINF, mo1 = NEGINF, l0 = 0.f, l1 = 0.f;
    float oacc[8][4] = {};
    for (int nc = 0; nc < 64; nc++) {
        int n0 = nc * 64;
        __syncthreads();
#pragma unroll
        for (int i = 0; i < 16; i++) {
            int e = t + i * 256;
            int d = e >> 6, nn = e & 63;
            sK[d * 72 + nn] = tf32one(kb_[(size_t)d * Nn + n0 + nn]);
            sV[d * 72 + nn] = tf32one(vb[(size_t)d * Nn + n0 + nn]);
        }
        __syncthreads();
        float c[8][4] = {};
#pragma unroll
        for (int ks = 0; ks < 8; ks++) {
            int kb = ks * 8 + ctg;
#pragma unroll
            for (int nf = 0; nf < 8; nf++) {
                int nb = nf * 8 + gid;
                uint32_t bb[2];
                bb[0] = sK[kb * 72 + nb];
                bb[1] = sK[(kb + 4) * 72 + nb];
                mma_m16n8k8(c[nf], qf[ks], bb);
            }
        }
        float tm0 = NEGINF, tm1 = NEGINF;
#pragma unroll
        for (int nf = 0; nf < 8; nf++) {
            tm0 = fmaxf(tm0, fmaxf(c[nf][0], c[nf][1]));
            tm1 = fmaxf(tm1, fmaxf(c[nf][2], c[nf][3]));
        }
#pragma unroll
        for (int off = 1; off <= 2; off <<= 1) {
            tm0 = fmaxf(tm0, __shfl_xor_sync(0xffffffffu, tm0, off));
            tm1 = fmaxf(tm1, __shfl_xor_sync(0xffffffffu, tm1, off));
        }
        float mn0 = fmaxf(mo0, tm0), mn1 = fmaxf(mo1, tm1);
        float s0 = __expf(mo0 - mn0), s1 = __expf(mo1 - mn1);
        float sum0 = 0.f, sum1 = 0.f;
#pragma unroll
        for (int nf = 0; nf < 8; nf++) {
            float p00 = __expf(c[nf][0] - mn0);
            float p01 = __expf(c[nf][1] - mn0);
            float p10 = __expf(c[nf][2] - mn1);
            float p11 = __expf(c[nf][3] - mn1);
            sum0 += p00 + p01;
            sum1 += p10 + p11;
            int nl = nf * 8 + 2 * ctg;
            sP[(mwb + gid) * 72 + nl]     = tf32one(p00);
            sP[(mwb + gid) * 72 + nl + 1] = tf32one(p01);
            sP[(mwb + gid + 8) * 72 + nl]     = tf32one(p10);
            sP[(mwb + gid + 8) * 72 + nl + 1] = tf32one(p11);
        }
#pragma unroll
        for (int off = 1; off <= 2; off <<= 1) {
            sum0 += __shfl_xor_sync(0xffffffffu, sum0, off);
            sum1 += __shfl_xor_sync(0xffffffffu, sum1, off);
        }
        l0 = l0 * s0 + sum0;
        l1 = l1 * s1 + sum1;
#pragma unroll
        for (int nf = 0; nf < 8; nf++) {
            oacc[nf][0] *= s0; oacc[nf][1] *= s0;
            oacc[nf][2] *= s1; oacc[nf][3] *= s1;
        }
        __syncwarp();
#pragma unroll
        for (int ks = 0; ks < 8; ks++) {
            int kb = ks * 8 + ctg;
            uint32_t a[4];
            a[0] = sP[(mwb + gid) * 72 + kb];
            a[1] = sP[(mwb + gid + 8) * 72 + kb];
            a[2] = sP[(mwb + gid) * 72 + kb + 4];
            a[3] = sP[(mwb + gid + 8) * 72 + kb + 4];
#pragma unroll
            for (int nf = 0; nf < 8; nf++) {
                int nb = nf * 8 + gid;
                uint32_t bb[2];
                bb[0] = sV[nb * 72 + kb];
                bb[1] = sV[nb * 72 + kb + 4];
                mma_m16n8k8(oacc[nf], a, bb);
            }
        }
        mo0 = mn0; mo1 = mn1;
    }
    float is0 = 1.0f / l0, is1 = 1.0f / l1;
    __syncthreads();
#pragma unroll
    for (int nf = 0; nf < 8; nf++) {
        int d0 = nf * 8 + 2 * ctg;
        int ml = mwb + gid;
        sO[d0 * 129 + ml]           = oacc[nf][0] * is0;
        sO[(d0 + 1) * 129 + ml]     = oacc[nf][1] * is0;
        sO[d0 * 129 + ml + 8]       = oacc[nf][2] * is1;
        sO[(d0 + 1) * 129 + ml + 8] = oacc[nf][3] * is1;
    }
    __syncthreads();
#pragma unroll
    for (int i = 0; i < 32; i++) {
        int e = t + i * 256;
        int d = e >> 7, m = e & 127;
        g_fgt[((size_t)b * Dd + d) * Nn + m0 + m] = sO[d * 129 + m];
    }
}

// ------------------- inter pre-bn: z2 = w_sem . fgt ------------------------
__global__ __launch_bounds__(128) void k_inter(const float* __restrict__ wsem) {
    __shared__ float sF[64][64];
    int b = blockIdx.y, n0 = blockIdx.x * 64, t = threadIdx.x;
    const float* fb = g_fgt + (size_t)b * Dd * Nn;
    for (int e = t; e < 4096; e += 128) {
        int d = e >> 6, nn = e & 63;
        sF[d][nn] = fb[(size_t)d * Nn + n0 + nn];
    }
    __syncthreads();
    float wr[64];
#pragma unroll
    for (int d = 0; d < 64; d++) wr[d] = wsem[t * 64 + d];
    float aS = 0.f, aQ = 0.f;
    for (int nn = 0; nn < 64; nn++) {
        float acc = 0.f;
#pragma unroll
        for (int d = 0; d < 64; d++) acc = fmaf(wr[d], sF[d][nn], acc);
        g_z2[((size_t)b * Nn + n0 + nn) * Oo + t] = acc;
        aS += acc;
        aQ = fmaf(acc, acc, aQ);
    }
    int blk = blockIdx.y * gridDim.x + blockIdx.x;
    g_p2s[(size_t)blk * Oo + t] = aS;
    g_p2q[(size_t)blk * Oo + t] = aQ;
}

// --------- bn stat finalize ------------------------------------------------
__global__ void k_bnstats(int which, int nblk, float invcnt,
                          const float* __restrict__ gamma, const float* __restrict__ beta) {
    int o = threadIdx.x;
    const float *ps, *pq;
    float *sc, *sh;
    if (which == 1) { ps = g_p1s; pq = g_p1q; sc = g_sc1; sh = g_sh1; }
    else if (which == 2) { ps = g_p2s; pq = g_p2q; sc = g_sc2; sh = g_sh2; }
    else { ps = g_p3s; pq = g_p3q; sc = g_sc3; sh = g_sh3; }
    float s = 0.f, q = 0.f;
    for (int i = 0; i < nblk; i++) {
        s += ps[(size_t)i * Oo + o];
        q += pq[(size_t)i * Oo + o];
    }
    float mean = s * invcnt;
    float var = q * invcnt - mean * mean;
    float scl = gamma[o] / sqrtf(var + 1e-5f);
    sc[o] = scl;
    sh[o] = beta[o] - mean * scl;
}

// --------- z3 = w_full . [lrelu(bn1(intra)); lrelu(bn2(inter))] ------------
__global__ __launch_bounds__(128) void k_z3(const float* __restrict__ wfull) {
    __shared__ float sC[16][256];
    __shared__ float sW[32][129];
    int bn0 = blockIdx.x * 16, t = threadIdx.x;
    for (int e = t; e < 16 * 256; e += 128) {
        int n = e >> 8, c = e & 255;
        int bn = bn0 + n;
        float pre;
        if (c < 128) {
            float s1 = g_sc1[c];
            float ym = (s1 >= 0.f) ? g_ymax[(size_t)bn * Oo + c] : g_ymin[(size_t)bn * Oo + c];
            pre = fmaf(s1, ym, g_sh1[c]);
        } else {
            int o = c - 128;
            pre = fmaf(g_sc2[o], g_z2[(size_t)bn * Oo + o], g_sh2[o]);
        }
        sC[n][c] = pre >= 0.f ? pre : NEG * pre;
    }
    float acc[16] = {};
    for (int ch = 0; ch < 8; ch++) {
        __syncthreads();
        for (int e = t; e < 32 * 128; e += 128) {
            int o = e >> 5, c = e & 31;
            sW[c][o] = wfull[(size_t)o * 256 + ch * 32 + c];
        }
        __syncthreads();
#pragma unroll 4
        for (int c = 0; c < 32; c++) {
            float w = sW[c][t];
            int cg = ch * 32 + c;
#pragma unroll
            for (int n = 0; n < 16; n++) acc[n] = fmaf(w, sC[n][cg], acc[n]);
        }
    }
    float aS = 0.f, aQ = 0.f;
#pragma unroll
    for (int n = 0; n < 16; n++) {
        float z = acc[n];
        g_z3[(size_t)(bn0 + n) * Oo + t] = z;
        aS += z;
        aQ = fmaf(z, z, aQ);
    }
    g_p3s[(size_t)blockIdx.x * Oo + t] = aS;
    g_p3q[(size_t)blockIdx.x * Oo + t] = aQ;
}

// --------- out[b,o,n] = lrelu(bn3(z3)) with transpose ----------------------
__global__ __launch_bounds__(256) void k_out(float* __restrict__ out) {
    __shared__ float tile[32][33];
    int b = blockIdx.z, o0 = blockIdx.y * 32, n0 = blockIdx.x * 32;
    int tx = threadIdx.x & 31, ty = threadIdx.x >> 5;
    float scl = g_sc3[o0 + tx], sh = g_sh3[o0 + tx];
#pragma unroll
    for (int i = 0; i < 4; i++) {
        int n = n0 + ty + i * 8;
        float v = fmaf(scl, g_z3[((size_t)b * Nn + n) * Oo + o0 + tx], sh);
        tile[ty + i * 8][tx] = v >= 0.f ? v : NEG * v;
    }
    __syncthreads();
#pragma unroll
    for (int i = 0; i < 4; i++) {
        int o = o0 + ty + i * 8;
        out[((size_t)b * Oo + o) * Nn + n0 + tx] = tile[tx][ty + i * 8];
    }
}

// ---------------------------------------------------------------------------
extern "C" void kernel_launch(void* const* d_in, const int* in_sizes, int n_in,
                              void* d_out, int out_size) {
    const float* f       = (const float*)d_in[0];
    const float* w_local = (const float*)d_in[1];
    const float* g_local = (const float*)d_in[2];
    const float* b_local = (const float*)d_in[3];
    const float* w_sem   = (const float*)d_in[4];
    const float* g_sem   = (const float*)d_in[5];
    const float* b_sem   = (const float*)d_in[6];
    const float* w_full  = (const float*)d_in[7];
    const float* g_full  = (const float*)d_in[8];
    const float* b_full  = (const float*)d_in[9];
    const float* wq = (const float*)d_in[10];
    const float* bq = (const float*)d_in[11];
    const float* wk = (const float*)d_in[12];
    const float* bk = (const float*)d_in[13];
    const float* wv = (const float*)d_in[14];
    const float* bv = (const float*)d_in[15];
    float* out = (float*)d_out;

    const int MM_SMEM = 128 * KST * 4;                 // 69632 bytes
    const int FL_SMEM = (64 + 128 + 64) * 72 * 4;      // 73728 bytes
    const int QK_SMEM = (64 * 65 + 192 * 64 + 192) * 4; // 66560 bytes
    cudaFuncSetAttribute(k_mm, cudaFuncAttributeMaxDynamicSharedMemorySize, MM_SMEM);
    cudaFuncSetAttribute(k_flash, cudaFuncAttributeMaxDynamicSharedMemorySize, FL_SMEM);
    cudaFuncSetAttribute(k_qkv, cudaFuncAttributeMaxDynamicSharedMemorySize, QK_SMEM);

    k_xx<<<64, 256>>>(f);
    k_tr<<<dim3(Nn / 32, Dd / 32, Bx), 256>>>(f);
    k_mm<<<dim3(32, 32, Bx), 256, MM_SMEM>>>(f);
    k_topk<<<Bx * Nn, 256>>>();
    k_projAB<<<Bx * Nn / 64, 256>>>(w_local);
    k_intra<<<Bx * Nn / 32, 256>>>(w_local);
    k_bnstats<<<1, 128>>>(1, 1024, 1.0f / (Bx * Nn * Kk), g_local, b_local);
    k_qkv<<<dim3(64, Bx), 256, QK_SMEM>>>(f, wq, bq, wk, bk, wv, bv);
    k_flash<<<dim3(32, Bx), 256, FL_SMEM>>>();
    k_inter<<<dim3(64, Bx), 128>>>(w_sem);
    k_bnstats<<<1, 128>>>(2, 256, 1.0f / (Bx * Nn), g_sem, b_sem);
    k_z3<<<Bx * Nn / 16, 128>>>(w_full);
    k_bnstats<<<1, 128>>>(3, 1024, 1.0f / (Bx * Nn), g_full, b_full);
    k_out<<<dim3(Nn / 32, Oo / 32, Bx), 256>>>(out);
}